// round 9
// baseline (speedup 1.0000x reference)
#include <cuda_runtime.h>
#include <cuda_fp16.h>
#include <cstdint>

#define ED   128
#define AD   64
#define THREADS 256
#define ROWB 272u        // padded row stride (136 fp16); 4r mod 32 banks -> ldmatrix conflict-free

// ---- shared memory layout (bytes) ----
#define A_OFF    0u          // 200 rows x 272 B = 54400
#define W_OFF    54400u      // 64 rows x 272 B = 17408 -> 71808 ; reused for float4 partials after GEMM
#define T_OFF    71808u      // 128 f32 -> 72320
#define C_OFF    72320u      // 64 f32 -> 72576
#define W2_OFF   72576u      // 64 f32 -> 72832
#define WARR_OFF 72832u      // 208 f32 -> 73664
#define B2_OFF   73664u
#define SMEM_BYTES 73680u    // x3 CTAs = 221 KB <= 228 KB carveout

static __device__ __forceinline__ uint32_t smem_u32(const void* p) {
    uint32_t a;
    asm("{ .reg .u64 t; cvta.to.shared.u64 t, %1; cvt.u32.u64 %0, t; }" : "=r"(a) : "l"(p));
    return a;
}

static __device__ __forceinline__ void ldsm_x4(uint32_t r[4], uint32_t addr) {
    asm volatile("ldmatrix.sync.aligned.m8n8.x4.shared.b16 {%0,%1,%2,%3}, [%4];"
        : "=r"(r[0]), "=r"(r[1]), "=r"(r[2]), "=r"(r[3]) : "r"(addr));
}

static __device__ __forceinline__ void mma16816(
    float c[4], const uint32_t a[4], uint32_t b0, uint32_t b1)
{
    asm volatile(
        "mma.sync.aligned.m16n8k16.row.col.f32.f16.f16.f32 "
        "{%0,%1,%2,%3}, {%4,%5,%6,%7}, {%8,%9}, {%0,%1,%2,%3};"
        : "+f"(c[0]), "+f"(c[1]), "+f"(c[2]), "+f"(c[3])
        : "r"(a[0]), "r"(a[1]), "r"(a[2]), "r"(a[3]), "r"(b0), "r"(b1));
}

__global__ void __launch_bounds__(THREADS, 3)
attn_din_kernel(const float* __restrict__ behav,
                const float* __restrict__ target,
                const float* __restrict__ W1,
                const float* __restrict__ b1,
                const float* __restrict__ W2,
                const float* __restrict__ b2,
                float* __restrict__ out)
{
    extern __shared__ char smem[];
    const int tid  = threadIdx.x;
    const int wid  = tid >> 5;
    const int lane = tid & 31;
    const int b    = blockIdx.x;
    const uint32_t su = smem_u32(smem);

    float* tS  = (float*)(smem + T_OFF);
    float* cS  = (float*)(smem + C_OFF);
    float* w2S = (float*)(smem + W2_OFF);
    float* wAr = (float*)(smem + WARR_OFF);

    // ---- stage small vectors + ALL 200 A rows (deep LDG stream) ----
    if (tid < ED) tS[tid]  = target[(size_t)b * ED + tid];
    if (tid < AD) w2S[tid] = W2[tid];
    if (tid == 0) *((float*)(smem + B2_OFF)) = b2[0];
    {
        const float4* bp = (const float4*)(behav + (size_t)b * 200 * ED);
        for (int r = wid; r < 200; r += 8) {
            float4 v = bp[r * (ED / 4) + lane];
            __half2 h01 = __floats2half2_rn(v.x, v.y);
            __half2 h23 = __floats2half2_rn(v.z, v.w);
            uint32_t off = (uint32_t)r * ROWB + (uint32_t)lane * 8u;
            *reinterpret_cast<uint2*>(smem + A_OFF + off) =
                make_uint2(*(uint32_t*)&h01, *(uint32_t*)&h23);
        }
    }
    __syncthreads();   // tS (and A) ready

    // ---- build per-batch weight W_b[a][k] = Wx + Wd + t[k]*Wm (fp16) ----
    for (int idx = tid; idx < ED * AD; idx += THREADS) {
        int k = idx >> 6, a = idx & 63;
        float w = W1[k * AD + a] + W1[(384 + k) * AD + a] + tS[k] * W1[(256 + k) * AD + a];
        uint32_t off = (uint32_t)a * ROWB + (uint32_t)k * 2u;
        *reinterpret_cast<__half*>(smem + W_OFF + off) = __float2half_rn(w);
    }
    // ---- c[a] = b1 + t @ (W_t - W_d), full-k by threads 0..63 (coalesced rows) ----
    if (tid < AD) {
        float acc = b1[tid];
#pragma unroll 4
        for (int k = 0; k < 128; k++)
            acc = fmaf(tS[k], W1[(128 + k) * AD + tid] - W1[(384 + k) * AD + tid], acc);
        cS[tid] = acc;
    }
    __syncthreads();   // W, cS ready

    const int g  = lane >> 2;
    const int t2 = (lane & 3) * 2;

    // B ldmatrix base (two n8-tiles per x4)
    const uint32_t b_base = su + W_OFF
        + (uint32_t)((lane & 7) + ((lane >> 4) << 3)) * ROWB
        + (uint32_t)(((lane >> 3) & 1) << 4);
    const float b2v = *((const float*)(smem + B2_OFF));

    // ---- GEMM + epilogue per m16 tile: warp w handles tiles {w, w+8} ----
    for (int tile = wid; tile < 13; tile += 8) {
        float acc[8][4];
#pragma unroll
        for (int n = 0; n < 8; n++)
#pragma unroll
            for (int i = 0; i < 4; i++) acc[n][i] = 0.f;

        const uint32_t a_base = su + A_OFF
            + (uint32_t)(tile * 16 + (lane & 15)) * ROWB + (uint32_t)((lane >> 4) << 4);
        // tile 12 rows 200-207 read into the W region -> finite fp16 garbage,
        // row-isolated in MMA, masked by the s<200 guard below.
#pragma unroll
        for (int ks = 0; ks < 8; ks++) {
            const uint32_t ko = (uint32_t)ks * 32u;
            uint32_t a[4];
            ldsm_x4(a, a_base + ko);
#pragma unroll
            for (int j = 0; j < 4; j++) {
                uint32_t bfr[4];
                ldsm_x4(bfr, b_base + (uint32_t)j * (16u * ROWB) + ko);
                mma16816(acc[2 * j],     a, bfr[0], bfr[1]);
                mma16816(acc[2 * j + 1], a, bfr[2], bfr[3]);
            }
        }

        // epilogue: z = b2 + sum_a relu(D+c)*W2 ; wAr = sigmoid(z) (0 if s>=200)
#pragma unroll
        for (int h = 0; h < 2; h++) {
            float z = 0.f;
#pragma unroll
            for (int n = 0; n < 8; n++) {
                int col = n * 8 + t2;
                float h0 = fmaxf(acc[n][2 * h]     + cS[col],     0.f);
                float h1 = fmaxf(acc[n][2 * h + 1] + cS[col + 1], 0.f);
                z = fmaf(h0, w2S[col], z);
                z = fmaf(h1, w2S[col + 1], z);
            }
            z += __shfl_xor_sync(0xFFFFFFFFu, z, 1);
            z += __shfl_xor_sync(0xFFFFFFFFu, z, 2);
            int s = tile * 16 + h * 8 + g;
            if ((lane & 3) == 0 && s < 208) {
                float wgt = (s < 200) ? (1.f / (1.f + __expf(-(z + b2v)))) : 0.f;
                wAr[s] = wgt;
            }
        }
    }
    __syncthreads();   // wAr ready; W region now dead -> reuse for partials

    // ---- weighted sum: thread (q=tid>>5, e4=lane) covers 25 rows x 4 e-vals ----
    {
        const int e4 = lane, q = tid >> 5;
        float4 acc4 = make_float4(0.f, 0.f, 0.f, 0.f);
        const char* base = smem + A_OFF + (uint32_t)e4 * 8u;
#pragma unroll 5
        for (int i = 0; i < 25; i++) {
            int s = q * 25 + i;
            uint2 d = *reinterpret_cast<const uint2*>(base + (uint32_t)s * ROWB);
            float2 f01 = __half22float2(*reinterpret_cast<__half2*>(&d.x));
            float2 f23 = __half22float2(*reinterpret_cast<__half2*>(&d.y));
            float ws = wAr[s];
            acc4.x = fmaf(ws, f01.x, acc4.x);
            acc4.y = fmaf(ws, f01.y, acc4.y);
            acc4.z = fmaf(ws, f23.x, acc4.z);
            acc4.w = fmaf(ws, f23.y, acc4.w);
        }
        ((float4*)(smem + W_OFF))[q * 32 + e4] = acc4;
    }
    __syncthreads();

    if (tid < 32) {
        const float4* p = (const float4*)(smem + W_OFF);
        float4 s0 = p[tid];
#pragma unroll
        for (int q = 1; q < 8; q++) {
            float4 v = p[q * 32 + tid];
            s0.x += v.x; s0.y += v.y; s0.z += v.z; s0.w += v.w;
        }
        *reinterpret_cast<float4*>(out + (size_t)b * ED + tid * 4) = s0;
    }
}

extern "C" void kernel_launch(void* const* d_in, const int* in_sizes, int n_in,
                              void* d_out, int out_size)
{
    const float* behav  = (const float*)d_in[0];
    const float* target = (const float*)d_in[1];
    const float* W1     = (const float*)d_in[2];
    const float* b1     = (const float*)d_in[3];
    const float* W2     = (const float*)d_in[4];
    const float* b2     = (const float*)d_in[5];
    float* out = (float*)d_out;

    const int B = in_sizes[1] / ED;   // 2048

    static bool attr_set = false;
    if (!attr_set) {
        cudaFuncSetAttribute(attn_din_kernel,
                             cudaFuncAttributeMaxDynamicSharedMemorySize, (int)SMEM_BYTES);
        attr_set = true;
    }

    attn_din_kernel<<<B, THREADS, SMEM_BYTES>>>(behav, target, W1, b1, W2, b2, out);
}

// round 10
// speedup vs baseline: 1.5656x; 1.5656x over previous
#include <cuda_runtime.h>
#include <cuda_fp16.h>
#include <cstdint>

#define ED   128
#define AD   64
#define THREADS 256
#define ROWB 272u        // padded row stride (136 fp16)

// ---- shared memory layout (bytes) ----
#define A_OFF     0u         // 128 rows x 272 B = 34816
#define W_OFF     34816u     // 64 rows x 272 B = 17408 -> 52224
#define W2_OFF    52224u     // 64 f32 -> 52480
#define WARR_OFF  52480u     // 128 f32 -> 52992
#define CPART_OFF 52992u     // 128 f32 (c partial halves, b1 folded into kh=0) -> 53504
#define PART_OFF  53504u     // 8 x 32 x float4 = 4096 -> 57600
#define B2_OFF    57600u
#define SMEM_BYTES 57608u    // x3 CTAs = 172.8 KB

static __device__ __forceinline__ void mma16816(
    float c[4], const uint32_t a[4], uint32_t b0, uint32_t b1)
{
    asm volatile(
        "mma.sync.aligned.m16n8k16.row.col.f32.f16.f16.f32 "
        "{%0,%1,%2,%3}, {%4,%5,%6,%7}, {%8,%9}, {%0,%1,%2,%3};"
        : "+f"(c[0]), "+f"(c[1]), "+f"(c[2]), "+f"(c[3])
        : "r"(a[0]), "r"(a[1]), "r"(a[2]), "r"(a[3]), "r"(b0), "r"(b1));
}

__global__ void __launch_bounds__(THREADS, 3)
attn_din_kernel(const float* __restrict__ behav,
                const float* __restrict__ target,
                const float* __restrict__ W1,
                const float* __restrict__ b1,
                const float* __restrict__ W2,
                const float* __restrict__ b2,
                float* __restrict__ out)
{
    extern __shared__ char smem[];
    const int tid  = threadIdx.x;
    const int wid  = tid >> 5;
    const int lane = tid & 31;
    const int b    = blockIdx.x;

    float* w2S = (float*)(smem + W2_OFF);
    float* wAr = (float*)(smem + WARR_OFF);
    float* cP  = (float*)(smem + CPART_OFF);

    if (tid < AD) w2S[tid] = W2[tid];
    if (tid == 64) *((float*)(smem + B2_OFF)) = b2[0];

    // ================= phase 0 (warp-specialized, fully parallel) =================
    if (wid < 4) {
        // warps 0-3: stage A half-0 (128 rows, fp16), warp w -> rows w, w+4, ...
        const float4* bp = (const float4*)(behav + (size_t)b * 200 * ED);
#pragma unroll 4
        for (int i = 0; i < 32; i++) {
            int r = wid + i * 4;
            float4 v = bp[r * 32 + lane];
            __half2 h01 = __floats2half2_rn(v.x, v.y);
            __half2 h23 = __floats2half2_rn(v.z, v.w);
            uint32_t off = (uint32_t)r * ROWB + (uint32_t)lane * 8u;
            *reinterpret_cast<uint2*>(smem + A_OFF + off) =
                make_uint2(*(uint32_t*)&h01, *(uint32_t*)&h23);
        }
    } else {
        // warps 4-7: build W_b[a][k] = Wx + Wd + t[k]*Wm (fp16) and c-partials.
        // thread j: column a = j&63, k-half kh = j>>6 (64 k's each).
        const int j  = tid - 128;
        const int a  = j & 63;
        const int kh = j >> 6;
        const float* tg  = target + (size_t)b * ED + kh * 64;
        const float* w1p = W1 + (size_t)(kh * 64) * AD + a;
        float cacc = (kh == 0) ? b1[a] : 0.f;
#pragma unroll 4
        for (int kk = 0; kk < 64; kk++) {
            float tk = tg[kk];                              // warp-broadcast, L2-hot
            float wx = w1p[kk * AD];                        // coalesced 128B
            float wt = w1p[(128 * AD) + kk * AD];
            float wm = w1p[(256 * AD) + kk * AD];
            float wd = w1p[(384 * AD) + kk * AD];
            float w  = wx + wd + tk * wm;
            int k = kh * 64 + kk;
            *reinterpret_cast<__half*>(smem + W_OFF + (uint32_t)a * ROWB + (uint32_t)k * 2u)
                = __float2half_rn(w);
            cacc = fmaf(tk, wt - wd, cacc);
        }
        cP[j] = cacc;                                       // c[a] = cP[a] + cP[64+a]
    }
    __syncthreads();   // A0, W, cP, w2S, b2 all ready

    const int g  = lane >> 2;
    const int t2 = (lane & 3) * 2;
    const int e4 = lane, q = tid >> 5;
    const float b2v = *((const float*)(smem + B2_OFF));

    float4 acc4 = make_float4(0.f, 0.f, 0.f, 0.f);          // persistent weighted sums

    for (int half = 0; half < 2; half++) {
        const int rows_real = half ? 72 : 128;

        if (half) {
            __syncthreads();   // wsum(half0) finished reading A
            // stage A half-1 (72 rows), all warps
            const float4* bp = (const float4*)(behav + (size_t)(b * 200 + 128) * ED);
            for (int r = wid; r < 72; r += 8) {
                float4 v = bp[r * 32 + lane];
                __half2 h01 = __floats2half2_rn(v.x, v.y);
                __half2 h23 = __floats2half2_rn(v.z, v.w);
                uint32_t off = (uint32_t)r * ROWB + (uint32_t)lane * 8u;
                *reinterpret_cast<uint2*>(smem + A_OFF + off) =
                    make_uint2(*(uint32_t*)&h01, *(uint32_t*)&h23);
            }
            __syncthreads();   // A1 ready
        }

        // ---- GEMM: warp w -> rows [16w,16w+16) x [64], scalar frag loads ----
        float acc[8][4];
#pragma unroll
        for (int n = 0; n < 8; n++)
#pragma unroll
            for (int i = 0; i < 4; i++) acc[n][i] = 0.f;

        if (wid * 16 < rows_real) {
#pragma unroll
            for (int ks = 0; ks < 8; ks++) {
                const uint32_t kb = (uint32_t)(ks * 16 + t2) * 2u;
                const char* base = smem + A_OFF + (uint32_t)(wid * 16 + g) * ROWB + kb;
                uint32_t a[4];
                a[0] = *(const uint32_t*)(base);
                a[1] = *(const uint32_t*)(base + 8 * ROWB);
                a[2] = *(const uint32_t*)(base + 16);
                a[3] = *(const uint32_t*)(base + 8 * ROWB + 16);
#pragma unroll
                for (int n = 0; n < 8; n++) {
                    const char* wb = smem + W_OFF + (uint32_t)(n * 8 + g) * ROWB + kb;
                    uint32_t b0  = *(const uint32_t*)(wb);
                    uint32_t b1r = *(const uint32_t*)(wb + 16);
                    mma16816(acc[n], a, b0, b1r);
                }
            }
        }

        // ---- epilogue: z = b2 + sum_a relu(D + c)*W2 ; wAr = sigmoid(z) ----
#pragma unroll
        for (int h = 0; h < 2; h++) {
            float z = 0.f;
#pragma unroll
            for (int n = 0; n < 8; n++) {
                int col = n * 8 + t2;
                float c0 = cP[col]     + cP[64 + col];
                float c1 = cP[col + 1] + cP[65 + col];
                float h0 = fmaxf(acc[n][2 * h]     + c0, 0.f);
                float h1 = fmaxf(acc[n][2 * h + 1] + c1, 0.f);
                z = fmaf(h0, w2S[col], z);
                z = fmaf(h1, w2S[col + 1], z);
            }
            z += __shfl_xor_sync(0xFFFFFFFFu, z, 1);
            z += __shfl_xor_sync(0xFFFFFFFFu, z, 2);
            int s = wid * 16 + h * 8 + g;
            if ((lane & 3) == 0) {
                float wgt = (s < rows_real) ? (1.f / (1.f + __expf(-(z + b2v)))) : 0.f;
                wAr[s] = wgt;
            }
        }
        __syncthreads();   // wAr ready

        // ---- weighted sum: thread (q, lane) -> 4 e-values x up to 16 rows ----
        {
            int lim = rows_real - q * 16;
            if (lim > 16) lim = 16;
            const char* base = smem + A_OFF + (uint32_t)e4 * 8u;
            for (int i = 0; i < lim; i++) {
                int s = q * 16 + i;
                uint2 d = *reinterpret_cast<const uint2*>(base + (uint32_t)s * ROWB);
                float2 f01 = __half22float2(*reinterpret_cast<__half2*>(&d.x));
                float2 f23 = __half22float2(*reinterpret_cast<__half2*>(&d.y));
                float ws = wAr[s];
                acc4.x = fmaf(ws, f01.x, acc4.x);
                acc4.y = fmaf(ws, f01.y, acc4.y);
                acc4.z = fmaf(ws, f23.x, acc4.z);
                acc4.w = fmaf(ws, f23.y, acc4.w);
            }
        }
    }

    // ---- cross-group reduce and store ----
    __syncthreads();   // everyone done reading A/wAr
    ((float4*)(smem + PART_OFF))[q * 32 + e4] = acc4;
    __syncthreads();

    if (tid < 32) {
        const float4* p = (const float4*)(smem + PART_OFF);
        float4 s0 = p[tid];
#pragma unroll
        for (int k = 1; k < 8; k++) {
            float4 v = p[k * 32 + tid];
            s0.x += v.x; s0.y += v.y; s0.z += v.z; s0.w += v.w;
        }
        *reinterpret_cast<float4*>(out + (size_t)b * ED + tid * 4) = s0;
    }
}

extern "C" void kernel_launch(void* const* d_in, const int* in_sizes, int n_in,
                              void* d_out, int out_size)
{
    const float* behav  = (const float*)d_in[0];
    const float* target = (const float*)d_in[1];
    const float* W1     = (const float*)d_in[2];
    const float* b1     = (const float*)d_in[3];
    const float* W2     = (const float*)d_in[4];
    const float* b2     = (const float*)d_in[5];
    float* out = (float*)d_out;

    const int B = in_sizes[1] / ED;   // 2048

    static bool attr_set = false;
    if (!attr_set) {
        cudaFuncSetAttribute(attn_din_kernel,
                             cudaFuncAttributeMaxDynamicSharedMemorySize, (int)SMEM_BYTES);
        attr_set = true;
    }

    attn_din_kernel<<<B, THREADS, SMEM_BYTES>>>(behav, target, W1, b1, W2, b2, out);
}